// round 7
// baseline (speedup 1.0000x reference)
#include <cuda_runtime.h>

// Problem constants (fixed by the reference)
#define SOUTN 8
#define P3N  8
#define P4N  4
#define NENT (P3N + P4N)   // 12 path entries total

constexpr int EPB     = 8;    // edges per batch (16 lanes per edge)
constexpr int THREADS = 128;
constexpr int SUPER   = 3;    // batches per super-iteration (amortizes constant reads)
constexpr int WST     = 208;  // per-edge W scratch stride; 208 mod 32 == 16 -> the warp's two
                              // groups read W on disjoint bank quads (conflict-free)
// per-edge W layout: [0,128) W3[p][i][k]; [128,192) W4[p][i][m]

__global__ __launch_bounds__(THREADS, 8)
void tp_kernel(const float* __restrict__ x0,
               const int*   __restrict__ i0,
               const float* __restrict__ x1,
               const float* __restrict__ C3,
               const float* __restrict__ C4,
               const int*   __restrict__ p3,
               const int*   __restrict__ p4,
               float* __restrict__ out,
               int E, int nSuper)
{
    __shared__ __align__(16) float sC3T[P3N * 64];    // [p][(i,k)][j] -> float4 per lane
    __shared__ __align__(16) float sC4T[P4N * 320];   // [p][(i,m)*20 + j*4+k], conflict-free stride
    __shared__ int   sp3[P3N * 3];
    __shared__ int   sp4[P4N * 4];
    __shared__ int   sFlat[NENT];   // (slot<<16)|(s0<<8)|so sorted by so; -1 = skipped (merged)
    __shared__ int   sMasks[2];     // [0]=flushMask over sFlat, [1]=zeroMask over so
    __shared__ int   sBSlot[NENT];  // build slot per p-index (t<8: W3 p, t>=8: W4 p-8)
    __shared__ int   sBAcc;         // bit t: build step t accumulates into its slot
    __shared__ __align__(16) float sW[SUPER][EPB][WST];

    const int tid = threadIdx.x;

    // ---- stage constants (once per block), transposing for vector loads ----
    for (int idx = tid; idx < 512; idx += THREADS) {
        int p = idx >> 6, r = idx & 63;
        int i = r >> 4, j = (r >> 2) & 3, k = r & 3;
        sC3T[p * 64 + (i * 4 + k) * 4 + j] = C3[idx];
    }
    for (int idx = tid; idx < 1024; idx += THREADS) {
        int p = idx >> 8, r = idx & 255;
        int i = r >> 6, j = (r >> 4) & 3, k = (r >> 2) & 3, m = r & 3;
        sC4T[p * 320 + (i * 4 + m) * 20 + j * 4 + k] = C4[idx];
    }
    if (tid < P3N * 3) sp3[tid] = p3[tid];
    if (tid < P4N * 4) sp4[tid] = p4[tid];
    __syncthreads();

    // ---- init: merge duplicate (s0,so) paths, build so-sorted flat list + masks ----
    if (tid == 0) {
        int es0[NENT], eso[NENT], slot[NENT], rep[NENT];
        for (int t = 0; t < NENT; t++) {
            if (t < P3N) { es0[t] = sp3[t * 3 + 0]; eso[t] = sp3[t * 3 + 2]; slot[t] = t * 16; }
            else { int p = t - P3N; es0[t] = sp4[p * 4 + 0]; eso[t] = sp4[p * 4 + 3]; slot[t] = 128 + p * 16; }
        }
        int accM = 0;
        for (int t = 0; t < NENT; t++) {
            rep[t] = t;
            for (int j = 0; j < t; j++)
                if (es0[j] == es0[t] && eso[j] == eso[t] && rep[j] == j) { rep[t] = j; break; }
            if (rep[t] != t) { slot[t] = slot[rep[t]]; accM |= 1 << t; }
            sBSlot[t] = slot[t];
        }
        sBAcc = accM;
        int c = 0, fm = 0, zm = 0;
        for (int so = 0; so < SOUTN; so++) {
            const int start = c;
            for (int t = 0; t < NENT; t++)
                if (eso[t] == so && rep[t] == t)
                    sFlat[c++] = (slot[t] << 16) | (es0[t] << 8) | so;
            if (c > start) fm |= 1 << (c - 1);
            else           zm |= 1 << so;
        }
        for (; c < NENT; c++) sFlat[c] = -1;    // merged-away entries: skipped tail
        sMasks[0] = fm; sMasks[1] = zm;
    }
    __syncthreads();

    // Block-constant metadata in registers.
    int ents[NENT];
    #pragma unroll
    for (int t = 0; t < NENT; t++) ents[t] = sFlat[t];
    const unsigned flushMask = (unsigned)sMasks[0];
    const unsigned zeroMask  = (unsigned)sMasks[1];
    const unsigned accMask   = (unsigned)sBAcc;

    const int g = tid >> 4;   // edge slot within batch (0..7)
    const int u = tid & 15;   // MUL index

    for (int sup = blockIdx.x; sup < nSuper; sup += gridDim.x) {
        // per-sub-batch edge ids + bounds, hoisted once (int32 arithmetic throughout)
        int  e_s[SUPER];
        bool ok_s[SUPER];
        int  idxs[SUPER];
        #pragma unroll
        for (int s = 0; s < SUPER; s++) {
            e_s[s]  = sup * (SUPER * EPB) + s * EPB + g;
            ok_s[s] = e_s[s] < E;
            idxs[s] = ok_s[s] ? __ldg(i0 + e_s[s]) : 0;
        }

        __syncwarp();   // previous super's main-phase reads of sW done before overwrite

        // prefetch first 4 gather vectors of sub-batch 0 (hidden behind build FMAs)
        const float* xr0 = x0 + idxs[0] * 512 + u * 4;
        const int ps0 = ents[0] < 0 ? 0 : ((ents[0] >> 8) & 0xFF);
        const int ps1 = ents[1] < 0 ? 0 : ((ents[1] >> 8) & 0xFF);
        const int ps2 = ents[2] < 0 ? 0 : ((ents[2] >> 8) & 0xFF);
        const int ps3 = ents[3] < 0 ? 0 : ((ents[3] >> 8) & 0xFF);
        float4 pv0 = __ldg(reinterpret_cast<const float4*>(xr0 + ps0 * 64));
        float4 pv1 = __ldg(reinterpret_cast<const float4*>(xr0 + ps1 * 64));
        float4 pv2 = __ldg(reinterpret_cast<const float4*>(xr0 + ps2 * 64));
        float4 pv3 = __ldg(reinterpret_cast<const float4*>(xr0 + ps3 * 64));

        // ---- W3 build: c loaded once per p, reused across SUPER sub-batches ----
        #pragma unroll
        for (int p = 0; p < P3N; p++) {
            const float4 c = *reinterpret_cast<const float4*>(sC3T + p * 64 + u * 4);
            const int seg  = sp3[p * 3 + 1];
            const int slot = sBSlot[p];
            const bool acc = (accMask >> p) & 1;
            #pragma unroll
            for (int s = 0; s < SUPER; s++) {
                float w = 0.f;
                if (ok_s[s]) {
                    const float4 b = __ldg(reinterpret_cast<const float4*>(x1 + e_s[s] * 32 + seg * 4));
                    w = b.x * c.x + b.y * c.y + b.z * c.z + b.w * c.w;
                }
                if (acc) w += sW[s][g][slot + u];   // merged path: accumulate (uniform pred)
                sW[s][g][slot + u] = w;
            }
        }
        // ---- W4 build: q (16 floats) loaded once per p, reused across sub-batches ----
        #pragma unroll
        for (int p = 0; p < P4N; p++) {
            const float* q = sC4T + p * 320 + u * 20;
            const float4 q0 = *reinterpret_cast<const float4*>(q);
            const float4 q1 = *reinterpret_cast<const float4*>(q + 4);
            const float4 q2 = *reinterpret_cast<const float4*>(q + 8);
            const float4 q3 = *reinterpret_cast<const float4*>(q + 12);
            const int segB = sp4[p * 4 + 1];
            const int segC = sp4[p * 4 + 2];
            const int slot = sBSlot[P3N + p];
            const bool acc = (accMask >> (P3N + p)) & 1;
            #pragma unroll
            for (int s = 0; s < SUPER; s++) {
                float w = 0.f;
                if (ok_s[s]) {
                    const float4 b = __ldg(reinterpret_cast<const float4*>(x1 + e_s[s] * 32 + segB * 4));
                    const float4 c = __ldg(reinterpret_cast<const float4*>(x1 + e_s[s] * 32 + segC * 4));
                    w  = b.x * (c.x * q0.x + c.y * q0.y + c.z * q0.z + c.w * q0.w);
                    w += b.y * (c.x * q1.x + c.y * q1.y + c.z * q1.z + c.w * q1.w);
                    w += b.z * (c.x * q2.x + c.y * q2.y + c.z * q2.z + c.w * q2.w);
                    w += b.w * (c.x * q3.x + c.y * q3.y + c.z * q3.z + c.w * q3.w);
                }
                if (acc) w += sW[s][g][slot + u];
                sW[s][g][slot + u] = w;
            }
        }
        __syncwarp();

        // ---- main contraction per sub-batch: flat entry stream with flush stores ----
        #pragma unroll
        for (int s = 0; s < SUPER; s++) {
            if (ok_s[s]) {
                const float* xr = x0 + idxs[s] * 512 + u * 4;
                const float* eg = sW[s][g];
                float* op = out + e_s[s] * 512 + u * 4;
                float4 acc = make_float4(0.f, 0.f, 0.f, 0.f);
                #pragma unroll
                for (int t = 0; t < NENT; t++) {
                    const int ent = ents[t];
                    if (ent >= 0) {                       // uniform; merged dups skipped
                        const int s0 = (ent >> 8) & 0xFF;
                        const int wo = ent >> 16;
                        float4 v;
                        if      (s == 0 && t == 0) v = pv0;
                        else if (s == 0 && t == 1) v = pv1;
                        else if (s == 0 && t == 2) v = pv2;
                        else if (s == 0 && t == 3) v = pv3;
                        else v = __ldg(reinterpret_cast<const float4*>(xr + s0 * 64));
                        const float4 w0 = *reinterpret_cast<const float4*>(eg + wo);
                        const float4 w1 = *reinterpret_cast<const float4*>(eg + wo + 4);
                        const float4 w2 = *reinterpret_cast<const float4*>(eg + wo + 8);
                        const float4 w3 = *reinterpret_cast<const float4*>(eg + wo + 12);
                        acc.x += v.x*w0.x + v.y*w1.x + v.z*w2.x + v.w*w3.x;
                        acc.y += v.x*w0.y + v.y*w1.y + v.z*w2.y + v.w*w3.y;
                        acc.z += v.x*w0.z + v.y*w1.z + v.z*w2.z + v.w*w3.z;
                        acc.w += v.x*w0.w + v.y*w1.w + v.z*w2.w + v.w*w3.w;
                        if (flushMask & (1u << t)) {      // uniform across warp
                            __stcs(reinterpret_cast<float4*>(op + (ent & 0xFF) * 64), acc);
                            acc = make_float4(0.f, 0.f, 0.f, 0.f);
                        }
                    }
                }
                #pragma unroll
                for (int so = 0; so < SOUTN; so++)
                    if (zeroMask & (1u << so))
                        __stcs(reinterpret_cast<float4*>(op + so * 64),
                               make_float4(0.f, 0.f, 0.f, 0.f));
            }
        }
    }
}

extern "C" void kernel_launch(void* const* d_in, const int* in_sizes, int n_in,
                              void* d_out, int out_size)
{
    const float* x0 = (const float*)d_in[0];
    const int*   i0 = (const int*)  d_in[1];
    const float* x1 = (const float*)d_in[2];
    const float* C3 = (const float*)d_in[3];
    const float* C4 = (const float*)d_in[4];
    const int*   p3 = (const int*)  d_in[5];
    const int*   p4 = (const int*)  d_in[6];
    float* out = (float*)d_out;

    const int E = in_sizes[1];                           // i0 element count = number of edges
    const int nBatch = (E + EPB - 1) / EPB;
    const int nSuper = (nBatch + SUPER - 1) / SUPER;
    int grid = nSuper < 1184 ? nSuper : 1184;            // 8 blocks/SM resident, grid-stride
    tp_kernel<<<grid, THREADS>>>(x0, i0, x1, C3, C4, p3, p4, out, E, nSuper);
}

// round 8
// speedup vs baseline: 1.5729x; 1.5729x over previous
#include <cuda_runtime.h>

// Problem constants (fixed by the reference)
#define SOUTN 8
#define P3N  8
#define P4N  4
#define NENT (P3N + P4N)   // 12 path entries total

constexpr int EPB     = 8;    // edges per batch (16 lanes per edge)
constexpr int THREADS = 128;
constexpr int SUPER   = 3;    // batches per super-iteration; main loop interleaves all 3
constexpr int WST     = 208;  // per-edge W scratch stride; 208 mod 32 == 16 -> the warp's two
                              // groups hit disjoint bank quads (conflict-free W reads)
// per-edge W layout: [0,128) W3[p][i][k]; [128,192) W4[p][i][m]

__global__ __launch_bounds__(THREADS, 8)
void tp_kernel(const float* __restrict__ x0,
               const int*   __restrict__ i0,
               const float* __restrict__ x1,
               const float* __restrict__ C3,
               const float* __restrict__ C4,
               const int*   __restrict__ p3,
               const int*   __restrict__ p4,
               float* __restrict__ out,
               int E, int nSuper)
{
    __shared__ __align__(16) float sC3T[P3N * 64];    // [p][(i,k)][j] -> float4 per lane
    __shared__ __align__(16) float sC4T[P4N * 320];   // [p][(i,m)*20 + j*4+k], conflict-free
    __shared__ int   sp3[P3N * 3];
    __shared__ int   sp4[P4N * 4];
    __shared__ int   sWO[NENT];     // W slot (float offset in edge scratch)
    __shared__ int   sXO[NENT];     // x0 segment float offset (s0*64)
    __shared__ int   sOO[NENT];     // out segment float offset (so*64)
    __shared__ int   sMasks[2];     // [0]=flushMask over entries, [1]=zeroMask over so
    __shared__ __align__(16) float sW[SUPER][EPB][WST];

    const int tid = threadIdx.x;

    // ---- stage constants (once per block), transposing for vector loads ----
    for (int idx = tid; idx < 512; idx += THREADS) {
        int p = idx >> 6, r = idx & 63;
        int i = r >> 4, j = (r >> 2) & 3, k = r & 3;
        sC3T[p * 64 + (i * 4 + k) * 4 + j] = C3[idx];
    }
    for (int idx = tid; idx < 1024; idx += THREADS) {
        int p = idx >> 8, r = idx & 255;
        int i = r >> 6, j = (r >> 4) & 3, k = (r >> 2) & 3, m = r & 3;
        sC4T[p * 320 + (i * 4 + m) * 20 + j * 4 + k] = C4[idx];
    }
    if (tid < P3N * 3) sp3[tid] = p3[tid];
    if (tid < P4N * 4) sp4[tid] = p4[tid];
    __syncthreads();

    // ---- build so-sorted entry arrays + flush/zero masks (simple, proven R5 logic) ----
    if (tid == 0) {
        int c = 0, fm = 0, zm = 0;
        for (int so = 0; so < SOUTN; so++) {
            const int start = c;
            for (int p = 0; p < P3N; p++)
                if (sp3[p * 3 + 2] == so) {
                    sWO[c] = p * 16; sXO[c] = sp3[p * 3 + 0] * 64; sOO[c] = so * 64; c++;
                }
            for (int p = 0; p < P4N; p++)
                if (sp4[p * 4 + 3] == so) {
                    sWO[c] = 128 + p * 16; sXO[c] = sp4[p * 4 + 0] * 64; sOO[c] = so * 64; c++;
                }
            if (c > start) fm |= 1 << (c - 1);
            else           zm |= 1 << so;
        }
        sMasks[0] = fm; sMasks[1] = zm;
    }
    __syncthreads();

    const unsigned flushMask = (unsigned)sMasks[0];
    const unsigned zeroMask  = (unsigned)sMasks[1];

    const int g = tid >> 4;   // edge slot within batch (0..7)
    const int u = tid & 15;   // MUL index

    for (int sup = blockIdx.x; sup < nSuper; sup += gridDim.x) {
        // per-sub-batch edge ids + bounds (int32 throughout; all offsets < 2^31 bytes)
        int  e_s[SUPER];
        bool ok_s[SUPER];
        int  idxs[SUPER];
        #pragma unroll
        for (int s = 0; s < SUPER; s++) {
            e_s[s]  = sup * (SUPER * EPB) + s * EPB + g;
            ok_s[s] = e_s[s] < E;
            idxs[s] = ok_s[s] ? __ldg(i0 + e_s[s]) : 0;
        }

        __syncwarp();   // previous super's main-phase reads of sW done before overwrite

        // ---- W3 build: c loaded once per p, reused across SUPER sub-batches ----
        #pragma unroll
        for (int p = 0; p < P3N; p++) {
            const float4 c = *reinterpret_cast<const float4*>(sC3T + p * 64 + u * 4);
            const int seg = sp3[p * 3 + 1];
            #pragma unroll
            for (int s = 0; s < SUPER; s++) {
                float w = 0.f;
                if (ok_s[s]) {
                    const float4 b = __ldg(reinterpret_cast<const float4*>(x1 + e_s[s] * 32 + seg * 4));
                    w = b.x * c.x + b.y * c.y + b.z * c.z + b.w * c.w;
                }
                sW[s][g][p * 16 + u] = w;
            }
        }
        // ---- W4 build: q (16 floats) loaded once per p, reused across sub-batches ----
        #pragma unroll
        for (int p = 0; p < P4N; p++) {
            const float* q = sC4T + p * 320 + u * 20;
            const float4 q0 = *reinterpret_cast<const float4*>(q);
            const float4 q1 = *reinterpret_cast<const float4*>(q + 4);
            const float4 q2 = *reinterpret_cast<const float4*>(q + 8);
            const float4 q3 = *reinterpret_cast<const float4*>(q + 12);
            const int segB = sp4[p * 4 + 1];
            const int segC = sp4[p * 4 + 2];
            #pragma unroll
            for (int s = 0; s < SUPER; s++) {
                float w = 0.f;
                if (ok_s[s]) {
                    const float4 b = __ldg(reinterpret_cast<const float4*>(x1 + e_s[s] * 32 + segB * 4));
                    const float4 c = __ldg(reinterpret_cast<const float4*>(x1 + e_s[s] * 32 + segC * 4));
                    w  = b.x * (c.x * q0.x + c.y * q0.y + c.z * q0.z + c.w * q0.w);
                    w += b.y * (c.x * q1.x + c.y * q1.y + c.z * q1.z + c.w * q1.w);
                    w += b.z * (c.x * q2.x + c.y * q2.y + c.z * q2.z + c.w * q2.w);
                    w += b.w * (c.x * q3.x + c.y * q3.y + c.z * q3.z + c.w * q3.w);
                }
                sW[s][g][128 + p * 16 + u] = w;
            }
        }
        __syncwarp();

        // ---- main contraction: (entry x sub-batch) INTERLEAVED -> 3 gathers in flight per t ----
        {
            const float* xr0 = x0 + (idxs[0] * 512 + u * 4);
            const float* xr1 = x0 + (idxs[1] * 512 + u * 4);
            const float* xr2 = x0 + (idxs[2] * 512 + u * 4);
            const int oo0 = e_s[0] * 512 + u * 4;
            const int oo1 = e_s[1] * 512 + u * 4;
            const int oo2 = e_s[2] * 512 + u * 4;
            const float* eg0 = sW[0][g];
            const float* eg1 = sW[1][g];
            const float* eg2 = sW[2][g];
            const bool k0 = ok_s[0], k1 = ok_s[1], k2 = ok_s[2];

            float4 a0 = make_float4(0.f, 0.f, 0.f, 0.f);
            float4 a1 = make_float4(0.f, 0.f, 0.f, 0.f);
            float4 a2 = make_float4(0.f, 0.f, 0.f, 0.f);

            #pragma unroll
            for (int t = 0; t < NENT; t++) {
                const int xo = sXO[t];                 // broadcast LDS, uniform
                const int wo = sWO[t];
                const float4 v0 = __ldg(reinterpret_cast<const float4*>(xr0 + xo));
                const float4 v1 = __ldg(reinterpret_cast<const float4*>(xr1 + xo));
                const float4 v2 = __ldg(reinterpret_cast<const float4*>(xr2 + xo));
                {
                    const float4 w0 = *reinterpret_cast<const float4*>(eg0 + wo);
                    const float4 w1 = *reinterpret_cast<const float4*>(eg0 + wo + 4);
                    const float4 w2 = *reinterpret_cast<const float4*>(eg0 + wo + 8);
                    const float4 w3 = *reinterpret_cast<const float4*>(eg0 + wo + 12);
                    a0.x += v0.x*w0.x + v0.y*w1.x + v0.z*w2.x + v0.w*w3.x;
                    a0.y += v0.x*w0.y + v0.y*w1.y + v0.z*w2.y + v0.w*w3.y;
                    a0.z += v0.x*w0.z + v0.y*w1.z + v0.z*w2.z + v0.w*w3.z;
                    a0.w += v0.x*w0.w + v0.y*w1.w + v0.z*w2.w + v0.w*w3.w;
                }
                {
                    const float4 w0 = *reinterpret_cast<const float4*>(eg1 + wo);
                    const float4 w1 = *reinterpret_cast<const float4*>(eg1 + wo + 4);
                    const float4 w2 = *reinterpret_cast<const float4*>(eg1 + wo + 8);
                    const float4 w3 = *reinterpret_cast<const float4*>(eg1 + wo + 12);
                    a1.x += v1.x*w0.x + v1.y*w1.x + v1.z*w2.x + v1.w*w3.x;
                    a1.y += v1.x*w0.y + v1.y*w1.y + v1.z*w2.y + v1.w*w3.y;
                    a1.z += v1.x*w0.z + v1.y*w1.z + v1.z*w2.z + v1.w*w3.z;
                    a1.w += v1.x*w0.w + v1.y*w1.w + v1.z*w2.w + v1.w*w3.w;
                }
                {
                    const float4 w0 = *reinterpret_cast<const float4*>(eg2 + wo);
                    const float4 w1 = *reinterpret_cast<const float4*>(eg2 + wo + 4);
                    const float4 w2 = *reinterpret_cast<const float4*>(eg2 + wo + 8);
                    const float4 w3 = *reinterpret_cast<const float4*>(eg2 + wo + 12);
                    a2.x += v2.x*w0.x + v2.y*w1.x + v2.z*w2.x + v2.w*w3.x;
                    a2.y += v2.x*w0.y + v2.y*w1.y + v2.z*w2.y + v2.w*w3.y;
                    a2.z += v2.x*w0.z + v2.y*w1.z + v2.z*w2.z + v2.w*w3.z;
                    a2.w += v2.x*w0.w + v2.y*w1.w + v2.z*w2.w + v2.w*w3.w;
                }
                if (flushMask & (1u << t)) {           // uniform across warp
                    const int oo = sOO[t];
                    if (k0) __stcs(reinterpret_cast<float4*>(out + oo0 + oo), a0);
                    if (k1) __stcs(reinterpret_cast<float4*>(out + oo1 + oo), a1);
                    if (k2) __stcs(reinterpret_cast<float4*>(out + oo2 + oo), a2);
                    a0 = make_float4(0.f, 0.f, 0.f, 0.f);
                    a1 = make_float4(0.f, 0.f, 0.f, 0.f);
                    a2 = make_float4(0.f, 0.f, 0.f, 0.f);
                }
            }
            // segments with no contributions must still be zeroed
            #pragma unroll
            for (int so = 0; so < SOUTN; so++)
                if (zeroMask & (1u << so)) {
                    const float4 z = make_float4(0.f, 0.f, 0.f, 0.f);
                    if (k0) __stcs(reinterpret_cast<float4*>(out + oo0 + so * 64), z);
                    if (k1) __stcs(reinterpret_cast<float4*>(out + oo1 + so * 64), z);
                    if (k2) __stcs(reinterpret_cast<float4*>(out + oo2 + so * 64), z);
                }
        }
    }
}

extern "C" void kernel_launch(void* const* d_in, const int* in_sizes, int n_in,
                              void* d_out, int out_size)
{
    const float* x0 = (const float*)d_in[0];
    const int*   i0 = (const int*)  d_in[1];
    const float* x1 = (const float*)d_in[2];
    const float* C3 = (const float*)d_in[3];
    const float* C4 = (const float*)d_in[4];
    const int*   p3 = (const int*)  d_in[5];
    const int*   p4 = (const int*)  d_in[6];
    float* out = (float*)d_out;

    const int E = in_sizes[1];                           // i0 element count = number of edges
    const int nBatch = (E + EPB - 1) / EPB;
    const int nSuper = (nBatch + SUPER - 1) / SUPER;
    int grid = nSuper < 1184 ? nSuper : 1184;            // 8 blocks/SM resident, grid-stride
    tp_kernel<<<grid, THREADS>>>(x0, i0, x1, C3, C4, p3, p4, out, E, nSuper);
}

// round 9
// speedup vs baseline: 1.7774x; 1.1300x over previous
#include <cuda_runtime.h>

// Problem constants (fixed by the reference)
#define SOUTN 8
#define P3N  8
#define P4N  4
#define NENT (P3N + P4N)   // 12 path entries total

constexpr int EPB     = 8;    // edges per batch (16 lanes per edge)
constexpr int THREADS = 128;
constexpr int SUPER   = 3;    // batches per super-iteration (amortizes constant reads)
constexpr int WST     = 200;  // per-edge W scratch stride; 200 mod 32 == 8 -> warp's two
                              // groups read W on disjoint bank quads (conflict-free)
constexpr int X1ST    = 36;   // staged-x1 row stride; rows land 4 banks apart (conflict-free)
// per-edge W layout: [0,128) W3[p][i][k]; [128,192) W4[p][i][m]

__global__ __launch_bounds__(THREADS, 7)   // reg budget 73 -> no ptxas squeeze at 64
void tp_kernel(const float* __restrict__ x0,
               const int*   __restrict__ i0,
               const float* __restrict__ x1,
               const float* __restrict__ C3,
               const float* __restrict__ C4,
               const int*   __restrict__ p3,
               const int*   __restrict__ p4,
               float* __restrict__ out,
               int E, int nSuper)
{
    __shared__ __align__(16) float sC3T[P3N * 64];    // [p][(i,k)][j] -> float4 per lane
    __shared__ __align__(16) float sC4T[P4N * 320];   // [p][(i,m)*20 + j*4+k], conflict-free
    __shared__ int   sp3[P3N * 3];
    __shared__ int   sp4[P4N * 4];
    __shared__ int   sFlat[NENT];   // (slot<<16)|(s0<<8)|so sorted by so
    __shared__ int   sMasks[2];     // [0]=flushMask, [1]=zeroMask
    __shared__ __align__(16) float sX1[4][6 * X1ST];  // per-warp staged x1 rows (6 edges)
    __shared__ __align__(16) float sW[SUPER][EPB][WST];

    const int tid = threadIdx.x;

    // ---- stage constants (once per block), transposing for vector loads ----
    for (int idx = tid; idx < 512; idx += THREADS) {
        int p = idx >> 6, r = idx & 63;
        int i = r >> 4, j = (r >> 2) & 3, k = r & 3;
        sC3T[p * 64 + (i * 4 + k) * 4 + j] = C3[idx];
    }
    for (int idx = tid; idx < 1024; idx += THREADS) {
        int p = idx >> 8, r = idx & 255;
        int i = r >> 6, j = (r >> 4) & 3, k = (r >> 2) & 3, m = r & 3;
        sC4T[p * 320 + (i * 4 + m) * 20 + j * 4 + k] = C4[idx];
    }
    if (tid < P3N * 3) sp3[tid] = p3[tid];
    if (tid < P4N * 4) sp4[tid] = p4[tid];
    __syncthreads();

    // ---- build so-sorted entry list + flush/zero masks (proven R5 logic) ----
    if (tid == 0) {
        int c = 0, fm = 0, zm = 0;
        for (int so = 0; so < SOUTN; so++) {
            const int start = c;
            for (int p = 0; p < P3N; p++)
                if (sp3[p * 3 + 2] == so)
                    sFlat[c++] = ((p * 16) << 16) | (sp3[p * 3 + 0] << 8) | so;
            for (int p = 0; p < P4N; p++)
                if (sp4[p * 4 + 3] == so)
                    sFlat[c++] = ((128 + p * 16) << 16) | (sp4[p * 4 + 0] << 8) | so;
            if (c > start) fm |= 1 << (c - 1);
            else           zm |= 1 << so;
        }
        sMasks[0] = fm; sMasks[1] = zm;
    }
    __syncthreads();

    int ents[NENT];
    #pragma unroll
    for (int t = 0; t < NENT; t++) ents[t] = sFlat[t];
    const unsigned flushMask = (unsigned)sMasks[0];
    const unsigned zeroMask  = (unsigned)sMasks[1];

    const int g    = tid >> 4;          // edge slot within batch (0..7)
    const int u    = tid & 15;          // MUL index
    const int w    = tid >> 5;          // warp id (owns groups 2w, 2w+1)
    const int lane = tid & 31;
    // this thread's staged-x1 base: row parity = which of the warp's two groups
    const float* xb = sX1[w] + (g & 1) * X1ST;   // row for sub s at + s*2*X1ST

    for (int sup = blockIdx.x; sup < nSuper; sup += gridDim.x) {
        const int supBase = sup * (SUPER * EPB);

        int  e_s[SUPER];
        bool ok_s[SUPER];
        int  idxs[SUPER];
        #pragma unroll
        for (int s = 0; s < SUPER; s++) {
            e_s[s]  = supBase + s * EPB + g;
            ok_s[s] = e_s[s] < E;
            idxs[s] = ok_s[s] ? __ldg(i0 + e_s[s]) : 0;
        }

        __syncwarp();   // warp's previous-super readers of sX1/sW done before overwrite

        // ---- stage this warp's 6 x1 rows (rows = (s, group-parity h)), all loads in flight ----
        {
            float* dst = sX1[w];
            {   // rows 0..3 (lanes 0..31)
                const int row = lane >> 3, f4 = lane & 7;
                const int s = row >> 1, h = row & 1;
                const int ee = supBase + s * EPB + 2 * w + h;
                float4 v = make_float4(0.f, 0.f, 0.f, 0.f);
                if (ee < E) v = __ldg(reinterpret_cast<const float4*>(x1 + ee * 32 + f4 * 4));
                *reinterpret_cast<float4*>(dst + row * X1ST + f4 * 4) = v;   // zeros if inactive
            }
            if (lane < 16) {   // rows 4..5
                const int row = 4 + (lane >> 3), f4 = lane & 7;
                const int h = row & 1;
                const int ee = supBase + 2 * EPB + 2 * w + h;
                float4 v = make_float4(0.f, 0.f, 0.f, 0.f);
                if (ee < E) v = __ldg(reinterpret_cast<const float4*>(x1 + ee * 32 + f4 * 4));
                *reinterpret_cast<float4*>(dst + row * X1ST + f4 * 4) = v;
            }
        }
        __syncwarp();

        // prefetch first 4 gather vectors of sub-batch 0 (hidden behind build FMAs)
        const float* xr0 = x0 + idxs[0] * 512 + u * 4;
        float4 pv0 = __ldg(reinterpret_cast<const float4*>(xr0 + ((ents[0] >> 8) & 0xFF) * 64));
        float4 pv1 = __ldg(reinterpret_cast<const float4*>(xr0 + ((ents[1] >> 8) & 0xFF) * 64));
        float4 pv2 = __ldg(reinterpret_cast<const float4*>(xr0 + ((ents[2] >> 8) & 0xFF) * 64));
        float4 pv3 = __ldg(reinterpret_cast<const float4*>(xr0 + ((ents[3] >> 8) & 0xFF) * 64));

        // ---- W3 build: c once per p; b from staged smem (29cyc); no guards (zero rows) ----
        #pragma unroll
        for (int p = 0; p < P3N; p++) {
            const float4 c = *reinterpret_cast<const float4*>(sC3T + p * 64 + u * 4);
            const int seg4 = sp3[p * 3 + 1] * 4;
            #pragma unroll
            for (int s = 0; s < SUPER; s++) {
                const float4 b = *reinterpret_cast<const float4*>(xb + s * (2 * X1ST) + seg4);
                sW[s][g][p * 16 + u] = b.x * c.x + b.y * c.y + b.z * c.z + b.w * c.w;
            }
        }
        // ---- W4 build: q once per p; b/c from staged smem ----
        #pragma unroll
        for (int p = 0; p < P4N; p++) {
            const float* q = sC4T + p * 320 + u * 20;
            const float4 q0 = *reinterpret_cast<const float4*>(q);
            const float4 q1 = *reinterpret_cast<const float4*>(q + 4);
            const float4 q2 = *reinterpret_cast<const float4*>(q + 8);
            const float4 q3 = *reinterpret_cast<const float4*>(q + 12);
            const int segB4 = sp4[p * 4 + 1] * 4;
            const int segC4 = sp4[p * 4 + 2] * 4;
            #pragma unroll
            for (int s = 0; s < SUPER; s++) {
                const float4 b = *reinterpret_cast<const float4*>(xb + s * (2 * X1ST) + segB4);
                const float4 c = *reinterpret_cast<const float4*>(xb + s * (2 * X1ST) + segC4);
                float wv;
                wv  = b.x * (c.x * q0.x + c.y * q0.y + c.z * q0.z + c.w * q0.w);
                wv += b.y * (c.x * q1.x + c.y * q1.y + c.z * q1.z + c.w * q1.w);
                wv += b.z * (c.x * q2.x + c.y * q2.y + c.z * q2.z + c.w * q2.w);
                wv += b.w * (c.x * q3.x + c.y * q3.y + c.z * q3.z + c.w * q3.w);
                sW[s][g][128 + p * 16 + u] = wv;
            }
        }
        __syncwarp();

        // ---- main contraction per sub-batch: flat 12-entry stream with flush stores ----
        #pragma unroll
        for (int s = 0; s < SUPER; s++) {
            if (ok_s[s]) {
                const float* xr = x0 + idxs[s] * 512 + u * 4;
                const float* eg = sW[s][g];
                float* op = out + e_s[s] * 512 + u * 4;
                float4 acc = make_float4(0.f, 0.f, 0.f, 0.f);
                #pragma unroll
                for (int t = 0; t < NENT; t++) {
                    const int ent = ents[t];
                    const int s0  = (ent >> 8) & 0xFF;
                    const int wo  = ent >> 16;
                    float4 v;
                    if      (s == 0 && t == 0) v = pv0;
                    else if (s == 0 && t == 1) v = pv1;
                    else if (s == 0 && t == 2) v = pv2;
                    else if (s == 0 && t == 3) v = pv3;
                    else v = __ldg(reinterpret_cast<const float4*>(xr + s0 * 64));
                    const float4 w0 = *reinterpret_cast<const float4*>(eg + wo);
                    const float4 w1 = *reinterpret_cast<const float4*>(eg + wo + 4);
                    const float4 w2 = *reinterpret_cast<const float4*>(eg + wo + 8);
                    const float4 w3 = *reinterpret_cast<const float4*>(eg + wo + 12);
                    acc.x += v.x*w0.x + v.y*w1.x + v.z*w2.x + v.w*w3.x;
                    acc.y += v.x*w0.y + v.y*w1.y + v.z*w2.y + v.w*w3.y;
                    acc.z += v.x*w0.z + v.y*w1.z + v.z*w2.z + v.w*w3.z;
                    acc.w += v.x*w0.w + v.y*w1.w + v.z*w2.w + v.w*w3.w;
                    if (flushMask & (1u << t)) {          // uniform across warp
                        __stcs(reinterpret_cast<float4*>(op + (ent & 0xFF) * 64), acc);
                        acc = make_float4(0.f, 0.f, 0.f, 0.f);
                    }
                }
                #pragma unroll
                for (int so = 0; so < SOUTN; so++)
                    if (zeroMask & (1u << so))
                        __stcs(reinterpret_cast<float4*>(op + so * 64),
                               make_float4(0.f, 0.f, 0.f, 0.f));
            }
        }
    }
}

extern "C" void kernel_launch(void* const* d_in, const int* in_sizes, int n_in,
                              void* d_out, int out_size)
{
    const float* x0 = (const float*)d_in[0];
    const int*   i0 = (const int*)  d_in[1];
    const float* x1 = (const float*)d_in[2];
    const float* C3 = (const float*)d_in[3];
    const float* C4 = (const float*)d_in[4];
    const int*   p3 = (const int*)  d_in[5];
    const int*   p4 = (const int*)  d_in[6];
    float* out = (float*)d_out;

    const int E = in_sizes[1];                           // i0 element count = number of edges
    const int nBatch = (E + EPB - 1) / EPB;
    const int nSuper = (nBatch + SUPER - 1) / SUPER;
    int grid = nSuper < 1036 ? nSuper : 1036;            // 7 blocks/SM resident, grid-stride
    tp_kernel<<<grid, THREADS>>>(x0, i0, x1, C3, C4, p3, p4, out, E, nSuper);
}